// round 7
// baseline (speedup 1.0000x reference)
#include <cuda_runtime.h>
#include <cuda_bf16.h>
#include <cstdint>
#include <math.h>

// Problem constants
#define BDIM 16384
#define IDIM 512
#define ODIM 256
#define GFEAT 15
#define KDIM 7680
#define HH 0.4f
#define NS 120            // K stages of BK=64
#define BK 64

// W^T (O, K) split bf16, flat
__device__ __align__(16) __nv_bfloat16 g_wt_hi[(size_t)ODIM * KDIM];
__device__ __align__(16) __nv_bfloat16 g_wt_lo[(size_t)ODIM * KDIM];
__device__ float g_d[IDIM * 5];

__device__ __forceinline__ void bsplit(float v, __nv_bfloat16& h, __nv_bfloat16& l) {
    h = __float2bfloat16(v);
    l = __float2bfloat16(v - __bfloat162float(h));
}

// ---------------------------------------------------------------------------
__global__ void k_dfactor(const float* __restrict__ d_raw) {
    int j = blockIdx.x * blockDim.x + threadIdx.x;
    if (j < IDIM * 5) g_d[j] = 0.99f * tanhf(d_raw[j]);
}

// ---------------------------------------------------------------------------
__global__ void k_pack(const float* __restrict__ bw,
                       const float* __restrict__ sw,
                       const float* __restrict__ sc,
                       const float* __restrict__ fw) {
    int t = blockIdx.x * blockDim.x + threadIdx.x;
    if (t >= ODIM * IDIM) return;
    int i = t & (IDIM - 1);
    int o = t >> 9;
    int oi = o * IDIM + i;
    float scaler = sc[oi];
    float v[GFEAT];
    v[0] = bw[oi];
#pragma unroll
    for (int gs = 0; gs < 8; gs++) v[1 + gs] = sw[(size_t)oi * 8 + gs] * scaler;
#pragma unroll
    for (int gf = 0; gf < 6; gf++) v[9 + gf] = fw[(size_t)oi * 6 + gf];
    size_t base = (size_t)o * KDIM + i * GFEAT;
#pragma unroll
    for (int g = 0; g < GFEAT; g++) {
        __nv_bfloat16 h, l;
        bsplit(v[g], h, l);
        g_wt_hi[base + g] = h;
        g_wt_lo[base + g] = l;
    }
}

// ---------------------------------------------------------------------------
// Basis evaluation for one (b,i): fills out[15]
// ---------------------------------------------------------------------------
__device__ __forceinline__ void eval_basis(float xv, int i, float* out) {
    out[0] = xv / (1.0f + __expf(-xv));

    float bb[11];
#pragma unroll
    for (int j = 0; j < 11; j++) {
        float gj  = -1.0f + HH * (float)(j - 3);
        float gj1 = -1.0f + HH * (float)(j - 2);
        bb[j] = (xv >= gj && xv < gj1) ? 1.0f : 0.0f;
    }
#pragma unroll
    for (int k = 1; k <= 3; k++) {
        float inv = 1.0f / (HH * (float)k);
#pragma unroll
        for (int j = 0; j < 11; j++) {
            if (j <= 10 - k) {
                float gj   = -1.0f + HH * (float)(j - 3);
                float gjk1 = -1.0f + HH * (float)(j + k + 1 - 3);
                bb[j] = (xv - gj) * inv * bb[j] + (gjk1 - xv) * inv * bb[j + 1];
            }
        }
    }
#pragma unroll
    for (int g = 0; g < 8; g++) out[1 + g] = bb[g];

    const float INVH = 2.5f;
    float d0 = g_d[i * 5 + 0], d1 = g_d[i * 5 + 1], d2 = g_d[i * 5 + 2],
          d3 = g_d[i * 5 + 3], d4 = g_d[i * 5 + 4];

    float t = fminf(fmaxf(xv, -1.0f), 1.0f);
    float phi[6];
#pragma unroll
    for (int m = 0; m < 6; m++) {
        float node = -1.0f + HH * (float)m;
        phi[m] = fmaxf(0.0f, 1.0f - fabsf(t - node) * INVH);
    }
    float mult = 1.0f;
#pragma unroll
    for (int dep = 0; dep < 8; dep++) {
        int idx = (int)floorf((t + 1.0f) * INVH);
        idx = max(0, min(idx, 4));
        float dv = (idx == 0) ? d0 : (idx == 1) ? d1 : (idx == 2) ? d2
                 : (idx == 3) ? d3 : d4;
        mult *= dv;
        float a = t - (-1.0f + (float)idx * HH);
        t = a * 5.0f - 1.0f;
        float u = (t + 1.0f) * 0.5f;
#pragma unroll
        for (int m = 0; m < 6; m++) {
            float node = -1.0f + HH * (float)m;
            float hatv = fmaxf(0.0f, 1.0f - fabsf(t - node) * INVH);
            float basev = (m == 0) ? (1.0f - u) : ((m == 5) ? u : 0.0f);
            phi[m] += mult * (hatv - basev);
        }
    }
#pragma unroll
    for (int m = 0; m < 6; m++) out[9 + m] = phi[m];
}

// ---------------------------------------------------------------------------
// Fused warp-specialized kernel: 128x256 CTA tile, grid 128.
//   warps 0-7 consumers (64x64 tiles, split-bf16 HMMA), warps 8-9 producers.
// ---------------------------------------------------------------------------
#define SSTR 72                         // smem row stride (elems); 144B
#define A_ELEMS (128 * SSTR)            // 9216
#define W_ELEMS (256 * SSTR)            // 18432
#define STAGEE (2 * A_ELEMS + 2 * W_ELEMS)   // 55296 elems
#define SMEM_BYTES (2 * STAGEE * 2)     // 221184 B

#define OFF_AH 0
#define OFF_AL A_ELEMS
#define OFF_WH (2 * A_ELEMS)
#define OFF_WL (2 * A_ELEMS + W_ELEMS)

__device__ __forceinline__ void cpa16(void* s, const void* g) {
    asm volatile("cp.async.cg.shared.global [%0], [%1], 16;\n"
                 :: "r"((unsigned int)__cvta_generic_to_shared(s)), "l"(g) : "memory");
}
#define CP_COMMIT() asm volatile("cp.async.commit_group;\n" ::: "memory")
#define CP_WAIT1()  asm volatile("cp.async.wait_group 1;\n" ::: "memory")
#define CP_WAIT0()  asm volatile("cp.async.wait_group 0;\n" ::: "memory")

#define BAR_SYNC(id)   asm volatile("bar.sync %0, 320;"   :: "r"(id) : "memory")
#define BAR_ARRIVE(id) asm volatile("bar.arrive %0, 320;" :: "r"(id) : "memory")

__device__ __forceinline__ void ldsm4(uint32_t& r0, uint32_t& r1,
                                      uint32_t& r2, uint32_t& r3, const void* p) {
    unsigned a = (unsigned)__cvta_generic_to_shared(p);
    asm volatile("ldmatrix.sync.aligned.m8n8.x4.shared.b16 {%0,%1,%2,%3}, [%4];"
                 : "=r"(r0), "=r"(r1), "=r"(r2), "=r"(r3) : "r"(a));
}
__device__ __forceinline__ void ldsm2(uint32_t& r0, uint32_t& r1, const void* p) {
    unsigned a = (unsigned)__cvta_generic_to_shared(p);
    asm volatile("ldmatrix.sync.aligned.m8n8.x2.shared.b16 {%0,%1}, [%2];"
                 : "=r"(r0), "=r"(r1) : "r"(a));
}

#define MMA16816(d, a, b)                                                  \
    asm volatile("mma.sync.aligned.m16n8k16.row.col.f32.bf16.bf16.f32 "    \
                 "{%0,%1,%2,%3}, {%4,%5,%6,%7}, {%8,%9}, {%0,%1,%2,%3};"   \
                 : "+f"(d[0]), "+f"(d[1]), "+f"(d[2]), "+f"(d[3])          \
                 : "r"(a[0]), "r"(a[1]), "r"(a[2]), "r"(a[3]),             \
                   "r"(b[0]), "r"(b[1]))

__global__ void __launch_bounds__(320, 1) k_fused(const float* __restrict__ x,
                                                  float* __restrict__ out) {
    extern __shared__ __nv_bfloat16 sm[];
    const int tid  = threadIdx.x;
    const int lane = tid & 31;
    const int warp = tid >> 5;
    const int bm = blockIdx.x * 128;

    if (warp < 8) {
        // ================= CONSUMERS =================
        const int wm = (warp & 1) * 64;
        const int wn = (warp >> 1) * 64;
        const int lr = lane >> 2;
        const int lc = lane & 3;
        const int l2 = lane & 15;
        const int arow = lane & 15, asel = (lane >> 4) << 3;
        const int brow = l2 & 7,  bsel = (l2 >> 3) << 3;

        auto loadW = [&](int s, int buf) {
            __nv_bfloat16* wh = sm + buf * STAGEE + OFF_WH;
            __nv_bfloat16* wl = sm + buf * STAGEE + OFF_WL;
            int kt = s * BK;
#pragma unroll
            for (int ch = 0; ch < 8; ch++) {
                int c = tid + ch * 256;
                int row = c >> 3, q = c & 7;
                size_t gsrc = (size_t)row * KDIM + kt + q * 8;
                int so = row * SSTR + q * 8;
                cpa16(wh + so, g_wt_hi + gsrc);
                cpa16(wl + so, g_wt_lo + gsrc);
            }
            CP_COMMIT();
        };

        float acc[4][8][4];
#pragma unroll
        for (int mm = 0; mm < 4; mm++)
#pragma unroll
            for (int nn = 0; nn < 8; nn++)
#pragma unroll
                for (int q = 0; q < 4; q++) acc[mm][nn][q] = 0.0f;

        loadW(0, 0);

        for (int s = 0; s < NS; s++) {
            int buf = s & 1;
            BAR_SYNC(1 + buf);                 // A[s] ready (producers arrived)
            if (s + 1 < NS) { loadW(s + 1, (s + 1) & 1); CP_WAIT1(); }
            else           { CP_WAIT0(); }

            const __nv_bfloat16* Ah = sm + buf * STAGEE + OFF_AH;
            const __nv_bfloat16* Al = sm + buf * STAGEE + OFF_AL;
            const __nv_bfloat16* Wh = sm + buf * STAGEE + OFF_WH;
            const __nv_bfloat16* Wl = sm + buf * STAGEE + OFF_WL;

#pragma unroll
            for (int kk = 0; kk < BK; kk += 16) {
                uint32_t bh[8][2], bl[8][2];
#pragma unroll
                for (int nn = 0; nn < 8; nn++) {
                    int o = (wn + nn * 8 + brow) * SSTR + kk + bsel;
                    ldsm2(bh[nn][0], bh[nn][1], Wh + o);
                    ldsm2(bl[nn][0], bl[nn][1], Wl + o);
                }
#pragma unroll
                for (int mm = 0; mm < 4; mm++) {
                    int o = (wm + mm * 16 + arow) * SSTR + kk + asel;
                    uint32_t ah[4], al[4];
                    ldsm4(ah[0], ah[1], ah[2], ah[3], Ah + o);
                    ldsm4(al[0], al[1], al[2], al[3], Al + o);
#pragma unroll
                    for (int nn = 0; nn < 8; nn++) {
                        MMA16816(acc[mm][nn], ah, bh[nn]);
                        MMA16816(acc[mm][nn], ah, bl[nn]);
                        MMA16816(acc[mm][nn], al, bh[nn]);
                    }
                }
            }
            BAR_ARRIVE(3 + buf);               // A[s] consumed
        }

        // epilogue
#pragma unroll
        for (int mm = 0; mm < 4; mm++) {
#pragma unroll
            for (int nn = 0; nn < 8; nn++) {
                int row = bm + wm + mm * 16 + lr;
                int col = wn + nn * 8 + 2 * lc;
                *(float2*)(out + (size_t)row * ODIM + col) =
                    make_float2(acc[mm][nn][0], acc[mm][nn][1]);
                *(float2*)(out + (size_t)(row + 8) * ODIM + col) =
                    make_float2(acc[mm][nn][2], acc[mm][nn][3]);
            }
        }
    } else {
        // ================= PRODUCERS (64 threads) =================
        const int p = tid - 256;
        for (int s = 0; s < NS; s++) {
            int buf = s & 1;
            if (s >= 2) BAR_SYNC(3 + buf);     // wait until A[buf] consumed
            int kt = s * BK;
            __nv_bfloat16* Ah = sm + buf * STAGEE + OFF_AH;
            __nv_bfloat16* Al = sm + buf * STAGEE + OFF_AL;
            int i0 = kt / GFEAT;
#pragma unroll
            for (int rr = 0; rr < 2; rr++) {
                int r = p + rr * 64;
                const float* xr = x + (size_t)(bm + r) * IDIM;
                __nv_bfloat16* ahr = Ah + r * SSTR;
                __nv_bfloat16* alr = Al + r * SSTR;
#pragma unroll
                for (int ii = 0; ii < 6; ii++) {
                    int i = i0 + ii;
                    int kbase = i * GFEAT;
                    if (kbase < kt + BK) {
                        float feats[GFEAT];
                        eval_basis(xr[i], i, feats);
#pragma unroll
                        for (int g = 0; g < GFEAT; g++) {
                            int j = kbase + g - kt;
                            if (j >= 0 && j < BK) {
                                __nv_bfloat16 h, l;
                                bsplit(feats[g], h, l);
                                ahr[j] = h;
                                alr[j] = l;
                            }
                        }
                    }
                }
            }
            BAR_ARRIVE(1 + buf);               // A[s] full
        }
    }
}

// ---------------------------------------------------------------------------
extern "C" void kernel_launch(void* const* d_in, const int* in_sizes, int n_in,
                              void* d_out, int out_size) {
    const float* x  = (const float*)d_in[0];
    const float* bw = (const float*)d_in[1];
    const float* sw = (const float*)d_in[2];
    const float* sc = (const float*)d_in[3];
    const float* fw = (const float*)d_in[4];
    const float* dr = (const float*)d_in[5];
    float* out = (float*)d_out;

    cudaFuncSetAttribute(k_fused, cudaFuncAttributeMaxDynamicSharedMemorySize,
                         SMEM_BYTES);

    k_dfactor<<<(IDIM * 5 + 255) / 256, 256>>>(dr);
    k_pack<<<(ODIM * IDIM + 255) / 256, 256>>>(bw, sw, sc, fw);
    k_fused<<<128, 320, SMEM_BYTES>>>(x, out);
}

// round 8
// speedup vs baseline: 4.2128x; 4.2128x over previous
#include <cuda_runtime.h>
#include <cuda_bf16.h>
#include <cstdint>
#include <math.h>

// Problem constants
#define BDIM 16384
#define IDIM 512
#define ODIM 256
#define GFEAT 15
#define KDIM 7680
#define HH 0.4f

// Scratch (device globals, 16B-aligned)
__device__ __align__(16) __nv_bfloat16 g_phi_hi[(size_t)BDIM * KDIM];
__device__ __align__(16) __nv_bfloat16 g_phi_lo[(size_t)BDIM * KDIM];
__device__ __align__(16) __nv_bfloat16 g_wt_hi[(size_t)ODIM * KDIM];   // (O, K)
__device__ __align__(16) __nv_bfloat16 g_wt_lo[(size_t)ODIM * KDIM];
__device__ float g_d[IDIM * 5];

__device__ __forceinline__ void bsplit(float v, __nv_bfloat16& h, __nv_bfloat16& l) {
    h = __float2bfloat16(v);
    l = __float2bfloat16(v - __bfloat162float(h));
}

// ---------------------------------------------------------------------------
__global__ void k_dfactor(const float* __restrict__ d_raw) {
    int j = blockIdx.x * blockDim.x + threadIdx.x;
    if (j < IDIM * 5) g_d[j] = 0.99f * tanhf(d_raw[j]);
}

// ---------------------------------------------------------------------------
// Pack W^T (O, K) in split bf16.  k = i*15 + g
// ---------------------------------------------------------------------------
__global__ void k_pack(const float* __restrict__ bw,
                       const float* __restrict__ sw,
                       const float* __restrict__ sc,
                       const float* __restrict__ fw) {
    int t = blockIdx.x * blockDim.x + threadIdx.x;
    if (t >= ODIM * IDIM) return;
    int i = t & (IDIM - 1);
    int o = t >> 9;
    int oi = o * IDIM + i;
    float scaler = sc[oi];
    float v[GFEAT];
    v[0] = bw[oi];
#pragma unroll
    for (int gs = 0; gs < 8; gs++) v[1 + gs] = sw[(size_t)oi * 8 + gs] * scaler;
#pragma unroll
    for (int gf = 0; gf < 6; gf++) v[9 + gf] = fw[(size_t)oi * 6 + gf];
    size_t base = (size_t)o * KDIM + i * GFEAT;
#pragma unroll
    for (int g = 0; g < GFEAT; g++) {
        __nv_bfloat16 h, l;
        bsplit(v[g], h, l);
        g_wt_hi[base + g] = h;
        g_wt_lo[base + g] = l;
    }
}

// ---------------------------------------------------------------------------
// Basis features: fp32 math, smem-staged coalesced split-bf16 output.
// ---------------------------------------------------------------------------
__global__ void __launch_bounds__(256) k_basis(const float* __restrict__ x) {
    __shared__ __align__(16) __nv_bfloat16 sh[256 * GFEAT];
    __shared__ __align__(16) __nv_bfloat16 sl[256 * GFEAT];

    const int tid = threadIdx.x;
    const int gid = blockIdx.x * 256 + tid;
    const int i = gid & (IDIM - 1);

    float xv = x[gid];
    float out[GFEAT];

    // silu
    out[0] = xv / (1.0f + __expf(-xv));

    // cubic B-splines (de Boor, unrolled; uniform grid)
    float bb[11];
#pragma unroll
    for (int j = 0; j < 11; j++) {
        float gj  = -1.0f + HH * (float)(j - 3);
        float gj1 = -1.0f + HH * (float)(j - 2);
        bb[j] = (xv >= gj && xv < gj1) ? 1.0f : 0.0f;
    }
#pragma unroll
    for (int k = 1; k <= 3; k++) {
        float inv = 1.0f / (HH * (float)k);
#pragma unroll
        for (int j = 0; j < 11; j++) {
            if (j <= 10 - k) {
                float gj   = -1.0f + HH * (float)(j - 3);
                float gjk1 = -1.0f + HH * (float)(j + k + 1 - 3);
                bb[j] = (xv - gj) * inv * bb[j] + (gjk1 - xv) * inv * bb[j + 1];
            }
        }
    }
#pragma unroll
    for (int g = 0; g < 8; g++) out[1 + g] = bb[g];

    // fractal bases, depth-8 IFS
    const float INVH = 2.5f;
    float d0 = g_d[i * 5 + 0], d1 = g_d[i * 5 + 1], d2 = g_d[i * 5 + 2],
          d3 = g_d[i * 5 + 3], d4 = g_d[i * 5 + 4];

    float t = fminf(fmaxf(xv, -1.0f), 1.0f);
    float phi[6];
#pragma unroll
    for (int m = 0; m < 6; m++) {
        float node = -1.0f + HH * (float)m;
        phi[m] = fmaxf(0.0f, 1.0f - fabsf(t - node) * INVH);
    }
    float mult = 1.0f;
#pragma unroll
    for (int dep = 0; dep < 8; dep++) {
        int idx = (int)floorf((t + 1.0f) * INVH);
        idx = max(0, min(idx, 4));
        float dv = (idx == 0) ? d0 : (idx == 1) ? d1 : (idx == 2) ? d2
                 : (idx == 3) ? d3 : d4;
        mult *= dv;
        float a = t - (-1.0f + (float)idx * HH);
        t = a * 5.0f - 1.0f;
        float u = (t + 1.0f) * 0.5f;
#pragma unroll
        for (int m = 0; m < 6; m++) {
            float node = -1.0f + HH * (float)m;
            float hatv = fmaxf(0.0f, 1.0f - fabsf(t - node) * INVH);
            float basev = (m == 0) ? (1.0f - u) : ((m == 5) ? u : 0.0f);
            phi[m] += mult * (hatv - basev);
        }
    }
#pragma unroll
    for (int m = 0; m < 6; m++) out[9 + m] = phi[m];

    // split + stage in smem
#pragma unroll
    for (int g = 0; g < GFEAT; g++) {
        __nv_bfloat16 h, l;
        bsplit(out[g], h, l);
        sh[tid * GFEAT + g] = h;
        sl[tid * GFEAT + g] = l;
    }
    __syncthreads();

    // coalesced copy-out: 3840 bf16 = 480 uint4 per array
    size_t dstbase = (size_t)(blockIdx.x) * (256 * GFEAT);
    uint4* dh = (uint4*)(g_phi_hi + dstbase);
    uint4* dl = (uint4*)(g_phi_lo + dstbase);
    const uint4* svh = (const uint4*)sh;
    const uint4* svl = (const uint4*)sl;
#pragma unroll
    for (int t4 = tid; t4 < 480; t4 += 256) {
        dh[t4] = svh[t4];
        dl[t4] = svl[t4];
    }
}

// ---------------------------------------------------------------------------
// Split-bf16 HMMA GEMM: out(B,O) = Phi(B,K) @ W(K,O)
//   CTA tile 128 x 256 (full O), 8 warps x (64x64), BK=32, 2 stages.
//   acc += Ah*Bh + Ah*Bl + Al*Bh   (fp32 accum, mma.sync m16n8k16)
// ---------------------------------------------------------------------------
#define BM 128
#define BN 256
#define BK 32
#define NK (KDIM / BK)        // 240
#define SSTR 40               // bf16/row; 80B stride -> conflict-free ldmatrix
#define A_ELEMS (BM * SSTR)   // 5120
#define W_ELEMS (BN * SSTR)   // 10240
#define STAGEE (2 * A_ELEMS + 2 * W_ELEMS)   // 30720 elems
#define SMEM_BYTES (2 * STAGEE * 2)          // 122880 B

#define OFF_AH 0
#define OFF_AL A_ELEMS
#define OFF_WH (2 * A_ELEMS)
#define OFF_WL (2 * A_ELEMS + W_ELEMS)

__device__ __forceinline__ void cpa16(void* s, const void* g) {
    asm volatile("cp.async.cg.shared.global [%0], [%1], 16;\n"
                 :: "r"((unsigned int)__cvta_generic_to_shared(s)), "l"(g) : "memory");
}
#define CP_COMMIT() asm volatile("cp.async.commit_group;\n" ::: "memory")
#define CP_WAIT1()  asm volatile("cp.async.wait_group 1;\n" ::: "memory")
#define CP_WAIT0()  asm volatile("cp.async.wait_group 0;\n" ::: "memory")

__device__ __forceinline__ void ldsm4(uint32_t& r0, uint32_t& r1,
                                      uint32_t& r2, uint32_t& r3, const void* p) {
    unsigned a = (unsigned)__cvta_generic_to_shared(p);
    asm volatile("ldmatrix.sync.aligned.m8n8.x4.shared.b16 {%0,%1,%2,%3}, [%4];"
                 : "=r"(r0), "=r"(r1), "=r"(r2), "=r"(r3) : "r"(a));
}
__device__ __forceinline__ void ldsm2(uint32_t& r0, uint32_t& r1, const void* p) {
    unsigned a = (unsigned)__cvta_generic_to_shared(p);
    asm volatile("ldmatrix.sync.aligned.m8n8.x2.shared.b16 {%0,%1}, [%2];"
                 : "=r"(r0), "=r"(r1) : "r"(a));
}

#define MMA16816(d, a, b)                                                  \
    asm volatile("mma.sync.aligned.m16n8k16.row.col.f32.bf16.bf16.f32 "    \
                 "{%0,%1,%2,%3}, {%4,%5,%6,%7}, {%8,%9}, {%0,%1,%2,%3};"   \
                 : "+f"(d[0]), "+f"(d[1]), "+f"(d[2]), "+f"(d[3])          \
                 : "r"(a[0]), "r"(a[1]), "r"(a[2]), "r"(a[3]),             \
                   "r"(b[0]), "r"(b[1]))

__global__ void __launch_bounds__(256, 1) k_gemm(float* __restrict__ out) {
    extern __shared__ __nv_bfloat16 sm[];

    const int tid  = threadIdx.x;
    const int lane = tid & 31;
    const int warp = tid >> 5;
    const int bm = blockIdx.x * BM;
    const int wm = (warp & 1) * 64;   // 2x4 warp grid of 64x64 tiles
    const int wn = (warp >> 1) * 64;
    const int lr = lane >> 2;
    const int lc = lane & 3;
    const int l2 = lane & 15;
    const int arow = lane & 15, asel = (lane >> 4) << 3;
    const int brow = l2 & 7,   bsel = (l2 >> 3) << 3;

    // stage loader: A 512 chunks x2, W 1024 chunks x2 -> 12 cpa16/thread
    auto load_stage = [&](int kt, int s) {
        __nv_bfloat16* st = sm + s * STAGEE;
#pragma unroll
        for (int r = 0; r < 2; r++) {
            int c = tid + r * 256;
            int row = c >> 2, kc = c & 3;
            int so = row * SSTR + kc * 8;
            size_t ga = (size_t)(bm + row) * KDIM + kt + kc * 8;
            cpa16(st + OFF_AH + so, g_phi_hi + ga);
            cpa16(st + OFF_AL + so, g_phi_lo + ga);
        }
#pragma unroll
        for (int r = 0; r < 4; r++) {
            int c = tid + r * 256;
            int row = c >> 2, kc = c & 3;
            int so = row * SSTR + kc * 8;
            size_t gb = (size_t)row * KDIM + kt + kc * 8;
            cpa16(st + OFF_WH + so, g_wt_hi + gb);
            cpa16(st + OFF_WL + so, g_wt_lo + gb);
        }
        CP_COMMIT();
    };

    float acc[4][8][4];
#pragma unroll
    for (int mm = 0; mm < 4; mm++)
#pragma unroll
        for (int nn = 0; nn < 8; nn++)
#pragma unroll
            for (int q = 0; q < 4; q++) acc[mm][nn][q] = 0.0f;

    load_stage(0, 0);
    load_stage(BK, 1);

    for (int ks = 0; ks < NK; ks++) {
        if (ks + 2 < NK) { CP_WAIT1(); } else { CP_WAIT0(); }
        __syncthreads();

        const __nv_bfloat16* Ah = sm + (ks & 1) * STAGEE + OFF_AH;
        const __nv_bfloat16* Al = sm + (ks & 1) * STAGEE + OFF_AL;
        const __nv_bfloat16* Wh = sm + (ks & 1) * STAGEE + OFF_WH;
        const __nv_bfloat16* Wl = sm + (ks & 1) * STAGEE + OFF_WL;

#pragma unroll
        for (int kk = 0; kk < BK; kk += 16) {
            uint32_t bh[8][2], bl[8][2];
#pragma unroll
            for (int nn = 0; nn < 8; nn++) {
                int o = (wn + nn * 8 + brow) * SSTR + kk + bsel;
                ldsm2(bh[nn][0], bh[nn][1], Wh + o);
                ldsm2(bl[nn][0], bl[nn][1], Wl + o);
            }
#pragma unroll
            for (int mm = 0; mm < 4; mm++) {
                int o = (wm + mm * 16 + arow) * SSTR + kk + asel;
                uint32_t ah[4], al[4];
                ldsm4(ah[0], ah[1], ah[2], ah[3], Ah + o);
                ldsm4(al[0], al[1], al[2], al[3], Al + o);
#pragma unroll
                for (int nn = 0; nn < 8; nn++) {
                    MMA16816(acc[mm][nn], ah, bh[nn]);
                    MMA16816(acc[mm][nn], ah, bl[nn]);
                    MMA16816(acc[mm][nn], al, bh[nn]);
                }
            }
        }
        __syncthreads();
        if (ks + 2 < NK) load_stage((ks + 2) * BK, ks & 1);
    }

    // epilogue
#pragma unroll
    for (int mm = 0; mm < 4; mm++) {
#pragma unroll
        for (int nn = 0; nn < 8; nn++) {
            int row = bm + wm + mm * 16 + lr;
            int col = wn + nn * 8 + 2 * lc;
            *(float2*)(out + (size_t)row * ODIM + col) =
                make_float2(acc[mm][nn][0], acc[mm][nn][1]);
            *(float2*)(out + (size_t)(row + 8) * ODIM + col) =
                make_float2(acc[mm][nn][2], acc[mm][nn][3]);
        }
    }
}

// ---------------------------------------------------------------------------
extern "C" void kernel_launch(void* const* d_in, const int* in_sizes, int n_in,
                              void* d_out, int out_size) {
    const float* x  = (const float*)d_in[0];
    const float* bw = (const float*)d_in[1];
    const float* sw = (const float*)d_in[2];
    const float* sc = (const float*)d_in[3];
    const float* fw = (const float*)d_in[4];
    const float* dr = (const float*)d_in[5];
    float* out = (float*)d_out;

    cudaFuncSetAttribute(k_gemm, cudaFuncAttributeMaxDynamicSharedMemorySize,
                         SMEM_BYTES);

    k_dfactor<<<(IDIM * 5 + 255) / 256, 256>>>(dr);
    k_pack<<<(ODIM * IDIM + 255) / 256, 256>>>(bw, sw, sc, fw);
    k_basis<<<(BDIM * IDIM) / 256, 256>>>(x);
    k_gemm<<<BDIM / BM, 256, SMEM_BYTES>>>(out);
}